// round 2
// baseline (speedup 1.0000x reference)
#include <cuda_runtime.h>
#include <cstdint>

#define ROW_LEN 2048
#define NTHREADS 256
#define VPT 8       // values per thread
#define K_TOP 64
#define FULLMASK 0xffffffffu

// Monotone bijection: float -> uint32 such that float order == uint order.
__device__ __forceinline__ uint32_t f2u(float f) {
    uint32_t u = __float_as_uint(f);
    return (u & 0x80000000u) ? ~u : (u | 0x80000000u);
}
__device__ __forceinline__ float u2f(uint32_t u) {
    u = (u & 0x80000000u) ? (u & 0x7FFFFFFFu) : ~u;
    return __uint_as_float(u);
}

__global__ __launch_bounds__(NTHREADS)
void topk_softmax_kernel(const float* __restrict__ in, float* __restrict__ out) {
    const int row  = blockIdx.x;
    const int tid  = threadIdx.x;
    const int lane = tid & 31;
    const int wid  = tid >> 5;

    const float4* rp4 = reinterpret_cast<const float4*>(in + (size_t)row * ROW_LEN);
    float4*       op4 = reinterpret_cast<float4*>(out + (size_t)row * ROW_LEN);

    __shared__ int      hist[256];
    __shared__ int      s_wsum[8];
    __shared__ uint32_t s_ured[8];
    __shared__ float    s_fred[8];
    __shared__ uint32_t s_pref, s_vk, s_maxkey;
    __shared__ int      s_k, s_cnt;
    __shared__ float    s_sum;

    // ---- 1. Load row, transform to order-preserving uint keys ----
    float4 a = rp4[tid];
    float4 b = rp4[tid + NTHREADS];
    uint32_t key[VPT];
    key[0] = f2u(a.x); key[1] = f2u(a.y); key[2] = f2u(a.z); key[3] = f2u(a.w);
    key[4] = f2u(b.x); key[5] = f2u(b.y); key[6] = f2u(b.z); key[7] = f2u(b.w);

    // ---- 2. Row max (on keys; monotone) ----
    uint32_t mk = key[0];
    #pragma unroll
    for (int i = 1; i < VPT; i++) mk = max(mk, key[i]);
    #pragma unroll
    for (int o = 16; o; o >>= 1) mk = max(mk, __shfl_xor_sync(FULLMASK, mk, o));
    if (lane == 0) s_ured[wid] = mk;
    if (tid == 0) { s_pref = 0u; s_k = K_TOP; }
    __syncthreads();
    if (tid < 8) {
        uint32_t mm = s_ured[tid];
        #pragma unroll
        for (int o = 4; o; o >>= 1) mm = max(mm, __shfl_xor_sync(0xffu, mm, o));
        if (tid == 0) s_maxkey = mm;
    }

    // ---- 3. Radix select of the 64th-largest key (8-bit digits, early exit) ----
    uint32_t vk_u = 0;
    bool found = false;

    #pragma unroll
    for (int pass = 0; pass < 4; ++pass) {
        if (!found) {                         // uniform across block
            const int shift = 24 - pass * 8;
            hist[tid] = 0;
            __syncthreads();                  // also publishes s_pref/s_k (& s_maxkey)
            const uint32_t pref  = s_pref;
            const int      kcur  = s_k;
            const uint32_t pmask = (pass == 0) ? 0u : (0xFFFFFFFFu << (shift + 8));

            // warp-aggregated histogram
            #pragma unroll
            for (int i = 0; i < VPT; i++) {
                bool mm = ((key[i] & pmask) == pref);
                unsigned bal = __ballot_sync(FULLMASK, mm);
                if (mm) {
                    int bin = (key[i] >> shift) & 0xFF;
                    unsigned peers = __match_any_sync(bal, bin);
                    if (lane == (__ffs(peers) - 1))
                        atomicAdd(&hist[bin], __popc(peers));
                }
            }
            __syncthreads();

            // suffix scan via warp shuffles: S[t] = sum of hist[t..255]
            int h = hist[tid];
            int s = h;
            #pragma unroll
            for (int o = 1; o < 32; o <<= 1) {
                int t = __shfl_down_sync(FULLMASK, s, o);
                if (lane + o < 32) s += t;
            }
            if (lane == 0) s_wsum[wid] = s;   // warp total
            __syncthreads();
            int S = s;
            #pragma unroll
            for (int w = 0; w < 8; w++)
                if (w > wid) S += s_wsum[w];
            const int Sn = S - h;             // suffix at tid+1

            if (S >= kcur && Sn < kcur) {     // exactly one thread fires
                s_pref = pref | ((uint32_t)tid << shift);
                s_k    = kcur - Sn;
                s_cnt  = h;
            }
            __syncthreads();

            if (pass == 3) {
                vk_u  = s_pref;               // full 32-bit key
                found = true;
            } else if (s_cnt == 1) {
                // unique candidate with this prefix == the k-th key; find it
                const uint32_t fmask = 0xFFFFFFFFu << shift;
                const uint32_t p2    = s_pref;
                #pragma unroll
                for (int i = 0; i < VPT; i++)
                    if ((key[i] & fmask) == p2) s_vk = key[i];
                __syncthreads();
                vk_u  = s_vk;
                found = true;
            }
        }
    }

    const float rmax = u2f(s_maxkey);

    // ---- 4. Masked exp + sum ----
    float e[VPT];
    float sum = 0.0f;
    #pragma unroll
    for (int i = 0; i < VPT; i++) {
        float ev = (key[i] >= vk_u) ? __expf(u2f(key[i]) - rmax) : 0.0f;
        e[i] = ev;
        sum += ev;
    }
    #pragma unroll
    for (int o = 16; o; o >>= 1) sum += __shfl_xor_sync(FULLMASK, sum, o);
    if (lane == 0) s_fred[wid] = sum;
    __syncthreads();
    if (tid < 8) {
        float ss = s_fred[tid];
        #pragma unroll
        for (int o = 4; o; o >>= 1) ss += __shfl_xor_sync(0xffu, ss, o);
        if (tid == 0) s_sum = ss;
    }
    __syncthreads();

    const float inv = __fdividef(1.0f, s_sum);

    // ---- 5. Store (coalesced float4) ----
    float4 o1 = make_float4(e[0] * inv, e[1] * inv, e[2] * inv, e[3] * inv);
    float4 o2 = make_float4(e[4] * inv, e[5] * inv, e[6] * inv, e[7] * inv);
    op4[tid]            = o1;
    op4[tid + NTHREADS] = o2;
}

extern "C" void kernel_launch(void* const* d_in, const int* in_sizes, int n_in,
                              void* d_out, int out_size) {
    const float* in  = (const float*)d_in[0];
    float*       out = (float*)d_out;
    const int nrows = in_sizes[0] / ROW_LEN;   // 2*16*2048 = 65536
    topk_softmax_kernel<<<nrows, NTHREADS>>>(in, out);
}

// round 3
// speedup vs baseline: 1.5976x; 1.5976x over previous
#include <cuda_runtime.h>
#include <cstdint>

#define ROW_LEN 2048
#define NTHREADS 256
#define VPT 8       // values per thread
#define K_TOP 64
#define FULLMASK 0xffffffffu

// Monotone bijection: float -> uint32 such that float order == uint order.
__device__ __forceinline__ uint32_t f2u(float f) {
    uint32_t u = __float_as_uint(f);
    return (u & 0x80000000u) ? ~u : (u | 0x80000000u);
}
__device__ __forceinline__ float u2f(uint32_t u) {
    u = (u & 0x80000000u) ? (u & 0x7FFFFFFFu) : ~u;
    return __uint_as_float(u);
}

__global__ __launch_bounds__(NTHREADS)
void topk_softmax_kernel(const float* __restrict__ in, float* __restrict__ out) {
    const int row  = blockIdx.x;
    const int tid  = threadIdx.x;
    const int lane = tid & 31;
    const int wid  = tid >> 5;

    const float4* rp4 = reinterpret_cast<const float4*>(in + (size_t)row * ROW_LEN);
    float4*       op4 = reinterpret_cast<float4*>(out + (size_t)row * ROW_LEN);

    __shared__ int      hist[256];
    __shared__ int      s_wsum[8];
    __shared__ uint32_t s_ured[8];
    __shared__ float    s_fred[8];
    __shared__ uint32_t s_pref, s_vk, s_maxkey;
    __shared__ int      s_k, s_cnt;
    __shared__ float    s_sum;

    // ---- 1. Load row, transform to order-preserving uint keys ----
    float4 a = rp4[tid];
    float4 b = rp4[tid + NTHREADS];
    uint32_t key[VPT];
    key[0] = f2u(a.x); key[1] = f2u(a.y); key[2] = f2u(a.z); key[3] = f2u(a.w);
    key[4] = f2u(b.x); key[5] = f2u(b.y); key[6] = f2u(b.z); key[7] = f2u(b.w);

    // ---- 2. Row max (on keys; monotone) ----
    uint32_t mk = key[0];
    #pragma unroll
    for (int i = 1; i < VPT; i++) mk = max(mk, key[i]);
    #pragma unroll
    for (int o = 16; o; o >>= 1) mk = max(mk, __shfl_xor_sync(FULLMASK, mk, o));
    if (lane == 0) s_ured[wid] = mk;
    if (tid == 0) { s_pref = 0u; s_k = K_TOP; }
    __syncthreads();
    if (tid < 8) {
        uint32_t mm = s_ured[tid];
        #pragma unroll
        for (int o = 4; o; o >>= 1) mm = max(mm, __shfl_xor_sync(0xffu, mm, o));
        if (tid == 0) s_maxkey = mm;
    }

    // ---- 3. Radix select of the 64th-largest key (8-bit digits, early exit) ----
    uint32_t vk_u = 0;
    bool found = false;

    #pragma unroll
    for (int pass = 0; pass < 4; ++pass) {
        if (!found) {                         // uniform across block
            const int shift = 24 - pass * 8;
            hist[tid] = 0;
            __syncthreads();                  // publishes s_pref/s_k (+ s_maxkey)
            const uint32_t pref  = s_pref;
            const int      kcur  = s_k;
            const uint32_t pmask = (pass == 0) ? 0u : (0xFFFFFFFFu << (shift + 8));

            // plain-atomic histogram (only candidates matching prefix)
            #pragma unroll
            for (int i = 0; i < VPT; i++) {
                if ((key[i] & pmask) == pref)
                    atomicAdd(&hist[(key[i] >> shift) & 0xFF], 1);
            }
            __syncthreads();

            // suffix scan via warp shuffles: S[tid] = sum of hist[tid..255]
            const int h = hist[tid];
            int s = h;
            #pragma unroll
            for (int o = 1; o < 32; o <<= 1) {
                int t = __shfl_down_sync(FULLMASK, s, o);
                if (lane + o < 32) s += t;
            }
            if (lane == 0) s_wsum[wid] = s;   // warp total
            __syncthreads();
            int S = s;
            #pragma unroll
            for (int w = 1; w < 8; w++)
                if (w > wid) S += s_wsum[w];
            const int Sn = S - h;             // suffix at tid+1

            if (S >= kcur && Sn < kcur) {     // exactly one thread fires
                s_pref = pref | ((uint32_t)tid << shift);
                s_k    = kcur - Sn;
                s_cnt  = h;
            }
            __syncthreads();

            if (pass == 3) {
                vk_u  = s_pref;               // full 32-bit key
                found = true;
            } else if (s_cnt == 1) {
                // unique candidate with this prefix IS the k-th key; locate it
                const uint32_t fmask = 0xFFFFFFFFu << shift;
                const uint32_t p2    = s_pref;
                #pragma unroll
                for (int i = 0; i < VPT; i++)
                    if ((key[i] & fmask) == p2) s_vk = key[i];
                __syncthreads();
                vk_u  = s_vk;
                found = true;
            }
        }
    }

    const float rmax = u2f(s_maxkey);

    // ---- 4. Masked exp + sum ----
    float e[VPT];
    float sum = 0.0f;
    #pragma unroll
    for (int i = 0; i < VPT; i++) {
        float ev = (key[i] >= vk_u) ? __expf(u2f(key[i]) - rmax) : 0.0f;
        e[i] = ev;
        sum += ev;
    }
    #pragma unroll
    for (int o = 16; o; o >>= 1) sum += __shfl_xor_sync(FULLMASK, sum, o);
    if (lane == 0) s_fred[wid] = sum;
    __syncthreads();
    if (tid < 8) {
        float ss = s_fred[tid];
        #pragma unroll
        for (int o = 4; o; o >>= 1) ss += __shfl_xor_sync(0xffu, ss, o);
        if (tid == 0) s_sum = ss;
    }
    __syncthreads();

    const float inv = __fdividef(1.0f, s_sum);

    // ---- 5. Store (coalesced float4) ----
    float4 o1 = make_float4(e[0] * inv, e[1] * inv, e[2] * inv, e[3] * inv);
    float4 o2 = make_float4(e[4] * inv, e[5] * inv, e[6] * inv, e[7] * inv);
    op4[tid]            = o1;
    op4[tid + NTHREADS] = o2;
}

extern "C" void kernel_launch(void* const* d_in, const int* in_sizes, int n_in,
                              void* d_out, int out_size) {
    const float* in  = (const float*)d_in[0];
    float*       out = (float*)d_out;
    const int nrows = in_sizes[0] / ROW_LEN;   // 2*16*2048 = 65536
    topk_softmax_kernel<<<nrows, NTHREADS>>>(in, out);
}